// round 6
// baseline (speedup 1.0000x reference)
#include <cuda_runtime.h>
#include <cuda_bf16.h>
#include <math.h>
#include <stdint.h>

// x: (16, 256, 64, 64, 4) f32. Per (b,c) slab = 4096 float4 = 64 KB.
// Two-stream software pipeline through L2 (graph fork-join):
//   stream L (legacy): P0 P1 ... P7     (pool chunks, pure DRAM reads)
//   stream A:          S_i after ev(P_i) (scale chunk i: L2 reads + DRAM writes)
// Chunk = 2 batches = 32 MB, so chunk i is still L2-resident when S_i runs.
// Excite is recomputed redundantly per scale block (cheap).

#define NB 16
#define NC 256
#define SP 4096                       // float4 per (b,c)
#define CHUNK_B 2
#define NCHUNKS (NB / CHUNK_B)        // 8
#define CHUNK_BLOCKS (CHUNK_B * NC)   // 512
#define TPB 256
#define V_PER_T (SP / TPB)            // 16

__device__ float4 g_pooled[NB * NC];

// ---------------------------------------------------------------------------
// Pool: one block per (b,c). Default loads -> populate L2 for the S pass.
// ---------------------------------------------------------------------------
__global__ void __launch_bounds__(TPB) pool_kernel(const float* __restrict__ x,
                                                   int b0) {
    const int bc = b0 * NC + blockIdx.x;
    const float4* xp = reinterpret_cast<const float4*>(x) + (size_t)bc * SP;
    const int t = threadIdx.x;

    float4 m = make_float4(-INFINITY, -INFINITY, -INFINITY, -INFINITY);
    #pragma unroll
    for (int j = 0; j < V_PER_T; j++) {
        float4 v = xp[t + j * TPB];
        m.x = fmaxf(m.x, v.x);
        m.y = fmaxf(m.y, v.y);
        m.z = fmaxf(m.z, v.z);
        m.w = fmaxf(m.w, v.w);
    }
    #pragma unroll
    for (int o = 16; o > 0; o >>= 1) {
        m.x = fmaxf(m.x, __shfl_xor_sync(0xffffffffu, m.x, o));
        m.y = fmaxf(m.y, __shfl_xor_sync(0xffffffffu, m.y, o));
        m.z = fmaxf(m.z, __shfl_xor_sync(0xffffffffu, m.z, o));
        m.w = fmaxf(m.w, __shfl_xor_sync(0xffffffffu, m.w, o));
    }
    __shared__ float4 red[TPB / 32];
    const int lane = t & 31;
    const int warp = t >> 5;
    if (lane == 0) red[warp] = m;
    __syncthreads();
    if (t == 0) {
        float4 r = red[0];
        #pragma unroll
        for (int w = 1; w < TPB / 32; w++) {
            r.x = fmaxf(r.x, red[w].x);
            r.y = fmaxf(r.y, red[w].y);
            r.z = fmaxf(r.z, red[w].z);
            r.w = fmaxf(r.w, red[w].w);
        }
        g_pooled[bc] = r;
    }
}

// ---------------------------------------------------------------------------
// Scale: one block per (b,c). Redundant squeeze+excite, then out = x * u.
// x read with ldcs (consume from L2, evict-first), out streamed with stcs.
// ---------------------------------------------------------------------------
__global__ void __launch_bounds__(TPB) scale_kernel(const float* __restrict__ x,
                                                    const float* __restrict__ comp_w,
                                                    const float* __restrict__ comp_b,
                                                    const float* __restrict__ exc_w,
                                                    const float* __restrict__ exc_b,
                                                    float* __restrict__ out,
                                                    int b0) {
    const int bc = b0 * NC + blockIdx.x;
    const int b = bc >> 8;
    const int c = bc & 255;
    const int t = threadIdx.x;
    const int lane = t & 31;
    const int warp = t >> 5;

    __shared__ float4 red[TPB / 32];
    __shared__ float4 u_sh;

    // Squeeze: thread t = channel t over pooled[b,:]
    float4 p = g_pooled[b * NC + t];
    float s0 = p.x * comp_w[0 * NC + t];
    float s1 = p.y * comp_w[1 * NC + t];
    float s2 = p.z * comp_w[2 * NC + t];
    float s3 = p.w * comp_w[3 * NC + t];
    #pragma unroll
    for (int o = 16; o > 0; o >>= 1) {
        s0 += __shfl_xor_sync(0xffffffffu, s0, o);
        s1 += __shfl_xor_sync(0xffffffffu, s1, o);
        s2 += __shfl_xor_sync(0xffffffffu, s2, o);
        s3 += __shfl_xor_sync(0xffffffffu, s3, o);
    }
    if (lane == 0) red[warp] = make_float4(s0, s1, s2, s3);
    __syncthreads();
    if (t == 0) {
        float r  = comp_b[0];
        float xc = comp_b[1];
        float yc = comp_b[2];
        float zc = comp_b[3];
        #pragma unroll
        for (int w = 0; w < TPB / 32; w++) {
            r  += red[w].x;
            xc += red[w].y;
            yc += red[w].z;
            zc += red[w].w;
        }
        float u1r = r + xc + yc + zc;
        float u1x = xc - r - zc + yc;
        float u1y = yc + zc - r - xc;
        float u1z = zc - yc + xc - r;
        float r2 = u1r * exc_w[0 * NC + c] + exc_b[0 * NC + c];
        float x2 = u1x * exc_w[1 * NC + c] + exc_b[1 * NC + c];
        float y2 = u1y * exc_w[2 * NC + c] + exc_b[2 * NC + c];
        float z2 = u1z * exc_w[3 * NC + c] + exc_b[3 * NC + c];
        u_sh = make_float4(r2 + x2 + y2 + z2,
                           x2 - r2 - z2 + y2,
                           y2 + z2 - r2 - x2,
                           z2 - y2 + x2 - r2);
    }
    __syncthreads();
    const float4 u = u_sh;

    const size_t base = (size_t)bc * SP;
    const float4* xp = reinterpret_cast<const float4*>(x) + base;
    float4* op = reinterpret_cast<float4*>(out) + base;
    #pragma unroll
    for (int j = 0; j < V_PER_T; j++) {
        int idx = t + j * TPB;
        float4 s = __ldcs(&xp[idx]);
        __stcs(&op[idx], make_float4(s.x * u.x, s.y * u.y,
                                     s.z * u.z, s.w * u.w));
    }
}

extern "C" void kernel_launch(void* const* d_in, const int* in_sizes, int n_in,
                              void* d_out, int out_size) {
    const float* x      = (const float*)d_in[0];
    const float* comp_w = (const float*)d_in[1];
    const float* comp_b = (const float*)d_in[2];
    const float* exc_w  = (const float*)d_in[3];
    const float* exc_b  = (const float*)d_in[4];
    float* out = (float*)d_out;

    // Lazily created once (first call is the non-captured correctness run).
    static cudaStream_t sA = nullptr;
    static cudaEvent_t evP[NCHUNKS];
    static cudaEvent_t evJoin = nullptr;
    if (sA == nullptr) {
        cudaStreamCreateWithFlags(&sA, cudaStreamNonBlocking);
        for (int i = 0; i < NCHUNKS; i++)
            cudaEventCreateWithFlags(&evP[i], cudaEventDisableTiming);
        cudaEventCreateWithFlags(&evJoin, cudaEventDisableTiming);
    }

    // Fork-join pipeline: P_i on legacy stream 0, S_i on sA gated by ev(P_i).
    for (int i = 0; i < NCHUNKS; i++) {
        pool_kernel<<<CHUNK_BLOCKS, TPB, 0, 0>>>(x, i * CHUNK_B);
        cudaEventRecord(evP[i], 0);
        cudaStreamWaitEvent(sA, evP[i], 0);
        scale_kernel<<<CHUNK_BLOCKS, TPB, 0, sA>>>(x, comp_w, comp_b,
                                                   exc_w, exc_b, out,
                                                   i * CHUNK_B);
    }
    cudaEventRecord(evJoin, sA);
    cudaStreamWaitEvent(0, evJoin, 0);
}

// round 7
// speedup vs baseline: 1.2765x; 1.2765x over previous
#include <cuda_runtime.h>
#include <cuda_bf16.h>
#include <math.h>
#include <stdint.h>

// x: (16, 256, 64, 64, 4) f32. Per (b,c) slab = 4096 float4 = 64 KB.
// Serial chunked pipeline through L2, chunk = 4 batches = 64 MB (fits L2):
//   pool(q): read chunk from DRAM (fills L2), per-(b,c) max.
//   scale(q): re-read chunk (mostly L2 hits), write out streamed.
// 8 dependent launches; launch overhead measured ~0.5us each.
// Both kernels batch 8 float4 loads in registers for MLP.

#define NB 16
#define NC 256
#define SP 4096                     // float4 per (b,c)
#define CHUNK_B 4
#define NCHUNKS (NB / CHUNK_B)      // 4
#define CHUNK_BLOCKS (CHUNK_B * NC) // 1024
#define TPB 256
#define V_PER_T (SP / TPB)          // 16
#define GRP 8                       // loads in flight

__device__ float4 g_pooled[NB * NC];

// ---------------------------------------------------------------------------
__global__ void __launch_bounds__(TPB) pool_kernel(const float* __restrict__ x,
                                                   int b0) {
    const int bc = b0 * NC + blockIdx.x;
    const float4* xp = reinterpret_cast<const float4*>(x) + (size_t)bc * SP;
    const int t = threadIdx.x;

    float4 m = make_float4(-INFINITY, -INFINITY, -INFINITY, -INFINITY);
    #pragma unroll
    for (int j0 = 0; j0 < V_PER_T; j0 += GRP) {
        float4 v[GRP];
        #pragma unroll
        for (int j = 0; j < GRP; j++) v[j] = xp[t + (j0 + j) * TPB];
        #pragma unroll
        for (int j = 0; j < GRP; j++) {
            m.x = fmaxf(m.x, v[j].x);
            m.y = fmaxf(m.y, v[j].y);
            m.z = fmaxf(m.z, v[j].z);
            m.w = fmaxf(m.w, v[j].w);
        }
    }
    #pragma unroll
    for (int o = 16; o > 0; o >>= 1) {
        m.x = fmaxf(m.x, __shfl_xor_sync(0xffffffffu, m.x, o));
        m.y = fmaxf(m.y, __shfl_xor_sync(0xffffffffu, m.y, o));
        m.z = fmaxf(m.z, __shfl_xor_sync(0xffffffffu, m.z, o));
        m.w = fmaxf(m.w, __shfl_xor_sync(0xffffffffu, m.w, o));
    }
    __shared__ float4 red[TPB / 32];
    const int lane = t & 31;
    const int warp = t >> 5;
    if (lane == 0) red[warp] = m;
    __syncthreads();
    if (t == 0) {
        float4 r = red[0];
        #pragma unroll
        for (int w = 1; w < TPB / 32; w++) {
            r.x = fmaxf(r.x, red[w].x);
            r.y = fmaxf(r.y, red[w].y);
            r.z = fmaxf(r.z, red[w].z);
            r.w = fmaxf(r.w, red[w].w);
        }
        g_pooled[bc] = r;
    }
}

// ---------------------------------------------------------------------------
__global__ void __launch_bounds__(TPB) scale_kernel(const float* __restrict__ x,
                                                    const float* __restrict__ comp_w,
                                                    const float* __restrict__ comp_b,
                                                    const float* __restrict__ exc_w,
                                                    const float* __restrict__ exc_b,
                                                    float* __restrict__ out,
                                                    int b0) {
    const int bc = b0 * NC + blockIdx.x;
    const int b = bc >> 8;
    const int c = bc & 255;
    const int t = threadIdx.x;
    const int lane = t & 31;
    const int warp = t >> 5;

    __shared__ float4 red[TPB / 32];
    __shared__ float4 u_sh;

    // ---- Squeeze: thread t = channel t over pooled[b,:] ----
    float4 p = g_pooled[b * NC + t];
    float s0 = p.x * comp_w[0 * NC + t];
    float s1 = p.y * comp_w[1 * NC + t];
    float s2 = p.z * comp_w[2 * NC + t];
    float s3 = p.w * comp_w[3 * NC + t];
    #pragma unroll
    for (int o = 16; o > 0; o >>= 1) {
        s0 += __shfl_xor_sync(0xffffffffu, s0, o);
        s1 += __shfl_xor_sync(0xffffffffu, s1, o);
        s2 += __shfl_xor_sync(0xffffffffu, s2, o);
        s3 += __shfl_xor_sync(0xffffffffu, s3, o);
    }
    if (lane == 0) red[warp] = make_float4(s0, s1, s2, s3);
    __syncthreads();
    if (t == 0) {
        float r  = comp_b[0];
        float xc = comp_b[1];
        float yc = comp_b[2];
        float zc = comp_b[3];
        #pragma unroll
        for (int w = 0; w < TPB / 32; w++) {
            r  += red[w].x;
            xc += red[w].y;
            yc += red[w].z;
            zc += red[w].w;
        }
        float u1r = r + xc + yc + zc;
        float u1x = xc - r - zc + yc;
        float u1y = yc + zc - r - xc;
        float u1z = zc - yc + xc - r;
        float r2 = u1r * exc_w[0 * NC + c] + exc_b[0 * NC + c];
        float x2 = u1x * exc_w[1 * NC + c] + exc_b[1 * NC + c];
        float y2 = u1y * exc_w[2 * NC + c] + exc_b[2 * NC + c];
        float z2 = u1z * exc_w[3 * NC + c] + exc_b[3 * NC + c];
        u_sh = make_float4(r2 + x2 + y2 + z2,
                           x2 - r2 - z2 + y2,
                           y2 + z2 - r2 - x2,
                           z2 - y2 + x2 - r2);
    }
    __syncthreads();
    const float4 u = u_sh;

    // ---- Scale: batched loads (MLP=8), then batched streamed stores ----
    const size_t base = (size_t)bc * SP;
    const float4* xp = reinterpret_cast<const float4*>(x) + base;
    float4* op = reinterpret_cast<float4*>(out) + base;
    #pragma unroll
    for (int j0 = 0; j0 < V_PER_T; j0 += GRP) {
        float4 v[GRP];
        #pragma unroll
        for (int j = 0; j < GRP; j++) v[j] = __ldcs(&xp[t + (j0 + j) * TPB]);
        #pragma unroll
        for (int j = 0; j < GRP; j++) {
            __stcs(&op[t + (j0 + j) * TPB],
                   make_float4(v[j].x * u.x, v[j].y * u.y,
                               v[j].z * u.z, v[j].w * u.w));
        }
    }
}

extern "C" void kernel_launch(void* const* d_in, const int* in_sizes, int n_in,
                              void* d_out, int out_size) {
    const float* x      = (const float*)d_in[0];
    const float* comp_w = (const float*)d_in[1];
    const float* comp_b = (const float*)d_in[2];
    const float* exc_w  = (const float*)d_in[3];
    const float* exc_b  = (const float*)d_in[4];
    float* out = (float*)d_out;

    for (int q = 0; q < NCHUNKS; q++) {
        pool_kernel <<<CHUNK_BLOCKS, TPB>>>(x, q * CHUNK_B);
        scale_kernel<<<CHUNK_BLOCKS, TPB>>>(x, comp_w, comp_b, exc_w, exc_b,
                                            out, q * CHUNK_B);
    }
}

// round 8
// speedup vs baseline: 1.2788x; 1.0018x over previous
#include <cuda_runtime.h>
#include <cuda_bf16.h>
#include <math.h>
#include <stdint.h>

// x: (16, 256, 64, 64, 4) f32. Per (b,c) slab = 4096 float4 = 64 KB.
// Chunk = 4 batches = 64 MB. Serial launch chain:
//   L0: pool(c0)
//   Lq: combined scale(c_{q-1}) + pool(c_q)  -- balanced mixed R/W stream
//   L4: scale(c3)
// Combined grid = 3072: role = blockIdx.x%3; role 0 -> pool one slab (64KB R),
// roles 1,2 -> scale one HALF slab (32KB L2-read + 32KB streamed write), so
// pool and scale blocks have matched duration -> no write-only tail.

#define NB 16
#define NC 256
#define SP 4096                      // float4 per (b,c)
#define CHUNK_B 4
#define NCHUNKS (NB / CHUNK_B)       // 4
#define CHUNK_SLABS (CHUNK_B * NC)   // 1024
#define TPB 256
#define HSP (SP / 2)                 // 2048 float4 per half slab
#define GRP 8

__device__ float4 g_pooled[NB * NC];

// ---------------------------------------------------------------------------
__device__ __forceinline__ void do_pool(const float* __restrict__ x, int bc) {
    const float4* xp = reinterpret_cast<const float4*>(x) + (size_t)bc * SP;
    const int t = threadIdx.x;

    float4 m = make_float4(-INFINITY, -INFINITY, -INFINITY, -INFINITY);
    #pragma unroll
    for (int j0 = 0; j0 < SP / TPB; j0 += GRP) {
        float4 v[GRP];
        #pragma unroll
        for (int j = 0; j < GRP; j++) v[j] = xp[t + (j0 + j) * TPB];
        #pragma unroll
        for (int j = 0; j < GRP; j++) {
            m.x = fmaxf(m.x, v[j].x);
            m.y = fmaxf(m.y, v[j].y);
            m.z = fmaxf(m.z, v[j].z);
            m.w = fmaxf(m.w, v[j].w);
        }
    }
    #pragma unroll
    for (int o = 16; o > 0; o >>= 1) {
        m.x = fmaxf(m.x, __shfl_xor_sync(0xffffffffu, m.x, o));
        m.y = fmaxf(m.y, __shfl_xor_sync(0xffffffffu, m.y, o));
        m.z = fmaxf(m.z, __shfl_xor_sync(0xffffffffu, m.z, o));
        m.w = fmaxf(m.w, __shfl_xor_sync(0xffffffffu, m.w, o));
    }
    __shared__ float4 red[TPB / 32];
    const int lane = t & 31;
    const int warp = t >> 5;
    if (lane == 0) red[warp] = m;
    __syncthreads();
    if (t == 0) {
        float4 r = red[0];
        #pragma unroll
        for (int w = 1; w < TPB / 32; w++) {
            r.x = fmaxf(r.x, red[w].x);
            r.y = fmaxf(r.y, red[w].y);
            r.z = fmaxf(r.z, red[w].z);
            r.w = fmaxf(r.w, red[w].w);
        }
        g_pooled[bc] = r;
    }
}

// ---------------------------------------------------------------------------
// Scale one HALF slab of (b,c): redundant squeeze+excite, then out = x*u.
// ---------------------------------------------------------------------------
__device__ __forceinline__ void do_scale_half(const float* __restrict__ x,
                                              const float* __restrict__ comp_w,
                                              const float* __restrict__ comp_b,
                                              const float* __restrict__ exc_w,
                                              const float* __restrict__ exc_b,
                                              float* __restrict__ out,
                                              int bc, int half) {
    const int b = bc >> 8;
    const int c = bc & 255;
    const int t = threadIdx.x;
    const int lane = t & 31;
    const int warp = t >> 5;

    __shared__ float4 red[TPB / 32];
    __shared__ float4 u_sh;

    // Squeeze: thread t = channel t over pooled[b,:]
    float4 p = g_pooled[b * NC + t];
    float s0 = p.x * comp_w[0 * NC + t];
    float s1 = p.y * comp_w[1 * NC + t];
    float s2 = p.z * comp_w[2 * NC + t];
    float s3 = p.w * comp_w[3 * NC + t];
    #pragma unroll
    for (int o = 16; o > 0; o >>= 1) {
        s0 += __shfl_xor_sync(0xffffffffu, s0, o);
        s1 += __shfl_xor_sync(0xffffffffu, s1, o);
        s2 += __shfl_xor_sync(0xffffffffu, s2, o);
        s3 += __shfl_xor_sync(0xffffffffu, s3, o);
    }
    if (lane == 0) red[warp] = make_float4(s0, s1, s2, s3);
    __syncthreads();
    if (t == 0) {
        float r  = comp_b[0];
        float xc = comp_b[1];
        float yc = comp_b[2];
        float zc = comp_b[3];
        #pragma unroll
        for (int w = 0; w < TPB / 32; w++) {
            r  += red[w].x;
            xc += red[w].y;
            yc += red[w].z;
            zc += red[w].w;
        }
        float u1r = r + xc + yc + zc;
        float u1x = xc - r - zc + yc;
        float u1y = yc + zc - r - xc;
        float u1z = zc - yc + xc - r;
        float r2 = u1r * exc_w[0 * NC + c] + exc_b[0 * NC + c];
        float x2 = u1x * exc_w[1 * NC + c] + exc_b[1 * NC + c];
        float y2 = u1y * exc_w[2 * NC + c] + exc_b[2 * NC + c];
        float z2 = u1z * exc_w[3 * NC + c] + exc_b[3 * NC + c];
        u_sh = make_float4(r2 + x2 + y2 + z2,
                           x2 - r2 - z2 + y2,
                           y2 + z2 - r2 - x2,
                           z2 - y2 + x2 - r2);
    }
    __syncthreads();
    const float4 u = u_sh;

    const size_t base = (size_t)bc * SP + (size_t)half * HSP;
    const float4* xp = reinterpret_cast<const float4*>(x) + base;
    float4* op = reinterpret_cast<float4*>(out) + base;
    #pragma unroll
    for (int j0 = 0; j0 < HSP / TPB; j0 += GRP) {
        float4 v[GRP];
        #pragma unroll
        for (int j = 0; j < GRP; j++) v[j] = __ldcs(&xp[t + (j0 + j) * TPB]);
        #pragma unroll
        for (int j = 0; j < GRP; j++) {
            __stcs(&op[t + (j0 + j) * TPB],
                   make_float4(v[j].x * u.x, v[j].y * u.y,
                               v[j].z * u.z, v[j].w * u.w));
        }
    }
}

// ---------------------------------------------------------------------------
__global__ void __launch_bounds__(TPB) pool_only_kernel(const float* __restrict__ x,
                                                        int b0) {
    do_pool(x, b0 * NC + blockIdx.x);
}

__global__ void __launch_bounds__(TPB) scale_only_kernel(const float* __restrict__ x,
                                                         const float* __restrict__ comp_w,
                                                         const float* __restrict__ comp_b,
                                                         const float* __restrict__ exc_w,
                                                         const float* __restrict__ exc_b,
                                                         float* __restrict__ out,
                                                         int b0) {
    do_scale_half(x, comp_w, comp_b, exc_w, exc_b, out,
                  b0 * NC + (int)(blockIdx.x >> 1), blockIdx.x & 1);
}

__global__ void __launch_bounds__(TPB) combined_kernel(const float* __restrict__ x,
                                                       const float* __restrict__ comp_w,
                                                       const float* __restrict__ comp_b,
                                                       const float* __restrict__ exc_w,
                                                       const float* __restrict__ exc_b,
                                                       float* __restrict__ out,
                                                       int scale_b0, int pool_b0) {
    const int sid  = blockIdx.x / 3;
    const int role = blockIdx.x % 3;
    if (role == 0)
        do_pool(x, pool_b0 * NC + sid);
    else
        do_scale_half(x, comp_w, comp_b, exc_w, exc_b, out,
                      scale_b0 * NC + sid, role - 1);
}

extern "C" void kernel_launch(void* const* d_in, const int* in_sizes, int n_in,
                              void* d_out, int out_size) {
    const float* x      = (const float*)d_in[0];
    const float* comp_w = (const float*)d_in[1];
    const float* comp_b = (const float*)d_in[2];
    const float* exc_w  = (const float*)d_in[3];
    const float* exc_b  = (const float*)d_in[4];
    float* out = (float*)d_out;

    // Prologue: pool chunk 0
    pool_only_kernel<<<CHUNK_SLABS, TPB>>>(x, 0);
    // Steady state: scale(q) + pool(q+1), balanced mixed stream
    for (int q = 0; q + 1 < NCHUNKS; q++) {
        combined_kernel<<<3 * CHUNK_SLABS, TPB>>>(x, comp_w, comp_b,
                                                  exc_w, exc_b, out,
                                                  q * CHUNK_B,
                                                  (q + 1) * CHUNK_B);
    }
    // Epilogue: scale last chunk
    scale_only_kernel<<<2 * CHUNK_SLABS, TPB>>>(x, comp_w, comp_b,
                                                exc_w, exc_b, out,
                                                (NCHUNKS - 1) * CHUNK_B);
}

// round 9
// speedup vs baseline: 1.3402x; 1.0480x over previous
#include <cuda_runtime.h>
#include <cuda_bf16.h>
#include <math.h>
#include <stdint.h>

// x: (16, 256, 64, 64, 4) f32. Per (b,c) slab = 4096 float4 = 64 KB.
// Chunk = 2 batches = 32 MB. Serial chain (overhead ~0.5us/launch):
//   L0: pool(c0)
//   Lk (k=1..7): fused(scale c_{k-1}, pool c_k) -- EACH BLOCK does one pool
//       slab (DRAM read) AND one scale slab (L2 read + streamed write) with
//       the loads interleaved in the same loop -> per-SM mixed R/W stream.
//   L8: scale(c7)
// L2 footprint in steady state = 64 MB << 126 MB -> scale reads hit L2.

#define NB 16
#define NC 256
#define SP 4096                      // float4 per (b,c)
#define CHUNK_B 2
#define NCHUNKS (NB / CHUNK_B)       // 8
#define CHUNK_SLABS (CHUNK_B * NC)   // 512
#define PTPB 256                     // pool/scale-only kernels
#define FTPB 512                     // fused kernel
#define HSP (SP / 2)

__device__ float4 g_pooled[NB * NC];

// ---------------------------------------------------------------------------
// Squeeze+excite for (b,c): threads 0..255 participate; result in *u_out.
// Caller provides shared red[8] and u_sh. Must be followed by __syncthreads.
// ---------------------------------------------------------------------------
__device__ __forceinline__ void compute_u(const float* __restrict__ comp_w,
                                          const float* __restrict__ comp_b,
                                          const float* __restrict__ exc_w,
                                          const float* __restrict__ exc_b,
                                          int b, int c, int t,
                                          float4* red, float4* u_sh) {
    if (t < NC) {
        float4 p = g_pooled[b * NC + t];
        float s0 = p.x * comp_w[0 * NC + t];
        float s1 = p.y * comp_w[1 * NC + t];
        float s2 = p.z * comp_w[2 * NC + t];
        float s3 = p.w * comp_w[3 * NC + t];
        #pragma unroll
        for (int o = 16; o > 0; o >>= 1) {
            s0 += __shfl_xor_sync(0xffffffffu, s0, o);
            s1 += __shfl_xor_sync(0xffffffffu, s1, o);
            s2 += __shfl_xor_sync(0xffffffffu, s2, o);
            s3 += __shfl_xor_sync(0xffffffffu, s3, o);
        }
        if ((t & 31) == 0) red[t >> 5] = make_float4(s0, s1, s2, s3);
    }
    __syncthreads();
    if (t == 0) {
        float r  = comp_b[0];
        float xc = comp_b[1];
        float yc = comp_b[2];
        float zc = comp_b[3];
        #pragma unroll
        for (int w = 0; w < NC / 32; w++) {
            r  += red[w].x;
            xc += red[w].y;
            yc += red[w].z;
            zc += red[w].w;
        }
        float u1r = r + xc + yc + zc;
        float u1x = xc - r - zc + yc;
        float u1y = yc + zc - r - xc;
        float u1z = zc - yc + xc - r;
        float r2 = u1r * exc_w[0 * NC + c] + exc_b[0 * NC + c];
        float x2 = u1x * exc_w[1 * NC + c] + exc_b[1 * NC + c];
        float y2 = u1y * exc_w[2 * NC + c] + exc_b[2 * NC + c];
        float z2 = u1z * exc_w[3 * NC + c] + exc_b[3 * NC + c];
        *u_sh = make_float4(r2 + x2 + y2 + z2,
                            x2 - r2 - z2 + y2,
                            y2 + z2 - r2 - x2,
                            z2 - y2 + x2 - r2);
    }
}

// ---------------------------------------------------------------------------
// Pool-only (prologue): one block per slab.
// ---------------------------------------------------------------------------
__global__ void __launch_bounds__(PTPB) pool_kernel(const float* __restrict__ x,
                                                    int b0) {
    const int bc = b0 * NC + blockIdx.x;
    const float4* xp = reinterpret_cast<const float4*>(x) + (size_t)bc * SP;
    const int t = threadIdx.x;

    float4 m = make_float4(-INFINITY, -INFINITY, -INFINITY, -INFINITY);
    #pragma unroll
    for (int j0 = 0; j0 < SP / PTPB; j0 += 8) {
        float4 v[8];
        #pragma unroll
        for (int j = 0; j < 8; j++) v[j] = xp[t + (j0 + j) * PTPB];
        #pragma unroll
        for (int j = 0; j < 8; j++) {
            m.x = fmaxf(m.x, v[j].x);
            m.y = fmaxf(m.y, v[j].y);
            m.z = fmaxf(m.z, v[j].z);
            m.w = fmaxf(m.w, v[j].w);
        }
    }
    #pragma unroll
    for (int o = 16; o > 0; o >>= 1) {
        m.x = fmaxf(m.x, __shfl_xor_sync(0xffffffffu, m.x, o));
        m.y = fmaxf(m.y, __shfl_xor_sync(0xffffffffu, m.y, o));
        m.z = fmaxf(m.z, __shfl_xor_sync(0xffffffffu, m.z, o));
        m.w = fmaxf(m.w, __shfl_xor_sync(0xffffffffu, m.w, o));
    }
    __shared__ float4 red[PTPB / 32];
    if ((t & 31) == 0) red[t >> 5] = m;
    __syncthreads();
    if (t == 0) {
        float4 r = red[0];
        #pragma unroll
        for (int w = 1; w < PTPB / 32; w++) {
            r.x = fmaxf(r.x, red[w].x);
            r.y = fmaxf(r.y, red[w].y);
            r.z = fmaxf(r.z, red[w].z);
            r.w = fmaxf(r.w, red[w].w);
        }
        g_pooled[bc] = r;
    }
}

// ---------------------------------------------------------------------------
// Fused: block i scales slab i of chunk scale_b0 and pools slab i of chunk
// pool_b0, loads interleaved. FTPB=512: 8 float4 per thread for each role.
// ---------------------------------------------------------------------------
__global__ void __launch_bounds__(FTPB) fused_kernel(const float* __restrict__ x,
                                                     const float* __restrict__ comp_w,
                                                     const float* __restrict__ comp_b,
                                                     const float* __restrict__ exc_w,
                                                     const float* __restrict__ exc_b,
                                                     float* __restrict__ out,
                                                     int scale_b0, int pool_b0) {
    const int slab = blockIdx.x;             // 0..CHUNK_SLABS-1
    const int sbc = scale_b0 * NC + slab;
    const int pbc = pool_b0 * NC + slab;
    const int t = threadIdx.x;

    __shared__ float4 red[FTPB / 32];
    __shared__ float4 u_sh;

    compute_u(comp_w, comp_b, exc_w, exc_b, sbc >> 8, sbc & 255, t, red, &u_sh);
    __syncthreads();
    const float4 u = u_sh;

    const float4* pp = reinterpret_cast<const float4*>(x) + (size_t)pbc * SP;
    const float4* sp = reinterpret_cast<const float4*>(x) + (size_t)sbc * SP;
    float4* op = reinterpret_cast<float4*>(out) + (size_t)sbc * SP;

    float4 m = make_float4(-INFINITY, -INFINITY, -INFINITY, -INFINITY);
    #pragma unroll
    for (int j0 = 0; j0 < SP / FTPB; j0 += 4) {
        float4 pv[4], sv[4];
        #pragma unroll
        for (int j = 0; j < 4; j++) pv[j] = pp[t + (j0 + j) * FTPB];
        #pragma unroll
        for (int j = 0; j < 4; j++) sv[j] = __ldcs(&sp[t + (j0 + j) * FTPB]);
        #pragma unroll
        for (int j = 0; j < 4; j++) {
            m.x = fmaxf(m.x, pv[j].x);
            m.y = fmaxf(m.y, pv[j].y);
            m.z = fmaxf(m.z, pv[j].z);
            m.w = fmaxf(m.w, pv[j].w);
        }
        #pragma unroll
        for (int j = 0; j < 4; j++) {
            __stcs(&op[t + (j0 + j) * FTPB],
                   make_float4(sv[j].x * u.x, sv[j].y * u.y,
                               sv[j].z * u.z, sv[j].w * u.w));
        }
    }
    // Block max-reduce (16 warps)
    #pragma unroll
    for (int o = 16; o > 0; o >>= 1) {
        m.x = fmaxf(m.x, __shfl_xor_sync(0xffffffffu, m.x, o));
        m.y = fmaxf(m.y, __shfl_xor_sync(0xffffffffu, m.y, o));
        m.z = fmaxf(m.z, __shfl_xor_sync(0xffffffffu, m.z, o));
        m.w = fmaxf(m.w, __shfl_xor_sync(0xffffffffu, m.w, o));
    }
    __syncthreads();   // red[] reuse
    if ((t & 31) == 0) red[t >> 5] = m;
    __syncthreads();
    if (t == 0) {
        float4 r = red[0];
        #pragma unroll
        for (int w = 1; w < FTPB / 32; w++) {
            r.x = fmaxf(r.x, red[w].x);
            r.y = fmaxf(r.y, red[w].y);
            r.z = fmaxf(r.z, red[w].z);
            r.w = fmaxf(r.w, red[w].w);
        }
        g_pooled[pbc] = r;
    }
}

// ---------------------------------------------------------------------------
// Scale-only (epilogue): one block per half slab.
// ---------------------------------------------------------------------------
__global__ void __launch_bounds__(PTPB) scale_kernel(const float* __restrict__ x,
                                                     const float* __restrict__ comp_w,
                                                     const float* __restrict__ comp_b,
                                                     const float* __restrict__ exc_w,
                                                     const float* __restrict__ exc_b,
                                                     float* __restrict__ out,
                                                     int b0) {
    const int bc = b0 * NC + (int)(blockIdx.x >> 1);
    const int half = blockIdx.x & 1;
    const int t = threadIdx.x;

    __shared__ float4 red[PTPB / 32];
    __shared__ float4 u_sh;
    compute_u(comp_w, comp_b, exc_w, exc_b, bc >> 8, bc & 255, t, red, &u_sh);
    __syncthreads();
    const float4 u = u_sh;

    const size_t base = (size_t)bc * SP + (size_t)half * HSP;
    const float4* xp = reinterpret_cast<const float4*>(x) + base;
    float4* op = reinterpret_cast<float4*>(out) + base;
    #pragma unroll
    for (int j0 = 0; j0 < HSP / PTPB; j0 += 8) {
        float4 v[8];
        #pragma unroll
        for (int j = 0; j < 8; j++) v[j] = __ldcs(&xp[t + (j0 + j) * PTPB]);
        #pragma unroll
        for (int j = 0; j < 8; j++) {
            __stcs(&op[t + (j0 + j) * PTPB],
                   make_float4(v[j].x * u.x, v[j].y * u.y,
                               v[j].z * u.z, v[j].w * u.w));
        }
    }
}

extern "C" void kernel_launch(void* const* d_in, const int* in_sizes, int n_in,
                              void* d_out, int out_size) {
    const float* x      = (const float*)d_in[0];
    const float* comp_w = (const float*)d_in[1];
    const float* comp_b = (const float*)d_in[2];
    const float* exc_w  = (const float*)d_in[3];
    const float* exc_b  = (const float*)d_in[4];
    float* out = (float*)d_out;

    pool_kernel<<<CHUNK_SLABS, PTPB>>>(x, 0);
    for (int q = 0; q + 1 < NCHUNKS; q++) {
        fused_kernel<<<CHUNK_SLABS, FTPB>>>(x, comp_w, comp_b, exc_w, exc_b,
                                            out, q * CHUNK_B, (q + 1) * CHUNK_B);
    }
    scale_kernel<<<2 * CHUNK_SLABS, PTPB>>>(x, comp_w, comp_b, exc_w, exc_b,
                                            out, (NCHUNKS - 1) * CHUNK_B);
}